// round 1
// baseline (speedup 1.0000x reference)
#include <cuda_runtime.h>

#define BS   4
#define NN   2048
#define CIN  128
#define COUT 64
#define H    4
#define HD   256   // H*COUT

#define TI 128
#define TJ 128
#define TIP (TI + 1)   // pad for conflict-free transposed P

// Scratch (device globals: allocation-free)
__device__ float g_hs[BS * H * NN * COUT];   // [b][h][n][d] head-major
__device__ float g_el[BS * H * NN];
__device__ float g_er[BS * H * NN];
__device__ float g_emax[BS * H];

// ---------------- packed f32x2 helpers ----------------
__device__ __forceinline__ unsigned long long pack2(float x) {
    unsigned long long r;
    asm("mov.b64 %0, {%1, %1};" : "=l"(r) : "f"(x));
    return r;
}
__device__ __forceinline__ void ffma2(unsigned long long &c, unsigned long long a,
                                      unsigned long long b) {
    asm("fma.rn.f32x2 %0, %1, %2, %0;" : "+l"(c) : "l"(a), "l"(b));
}
__device__ __forceinline__ float2 unpack2(unsigned long long v) {
    float2 f;
    asm("mov.b64 {%0, %1}, %2;" : "=f"(f.x), "=f"(f.y) : "l"(v));
    return f;
}

// ---------------- K1: hs = xs @ W1 (per-head 64x64 tiles) + el/er ----------------
__global__ __launch_bounds__(256) void k1_gemm(const float* __restrict__ xs,
                                               const float* __restrict__ W1,
                                               const float* __restrict__ a_l,
                                               const float* __restrict__ a_r) {
    const int bx   = blockIdx.x;   // row tile (64 rows)
    const int head = blockIdx.y;
    const int b    = blockIdx.z;
    const int tid  = threadIdx.x;
    const int ig = tid >> 4, cg = tid & 15;
    const int r0 = ig * 4, c0 = cg * 4;

    __shared__ float As[32][68];
    __shared__ float Bs[32][68];
    __shared__ float sred[16][64];

    float acc[4][4] = {};
    const float* xbase = xs + ((size_t)(b * NN + bx * 64)) * CIN;
    const float* wbase = W1 + head * COUT;

    for (int kc = 0; kc < CIN; kc += 32) {
        // A tile (transposed): 64 rows x 32 k
        int lin = tid;
        #pragma unroll
        for (int t = 0; t < 2; t++, lin += 256) {
            int r = lin >> 3, k4 = lin & 7;
            float4 v = *(const float4*)(xbase + r * CIN + kc + k4 * 4);
            As[k4 * 4 + 0][r] = v.x; As[k4 * 4 + 1][r] = v.y;
            As[k4 * 4 + 2][r] = v.z; As[k4 * 4 + 3][r] = v.w;
        }
        // B tile: 32 k x 64 cols
        lin = tid;
        #pragma unroll
        for (int t = 0; t < 2; t++, lin += 256) {
            int k = lin >> 4, c4 = lin & 15;
            float4 v = *(const float4*)(wbase + (size_t)(kc + k) * HD + c4 * 4);
            *(float4*)&Bs[k][c4 * 4] = v;
        }
        __syncthreads();
        #pragma unroll
        for (int k = 0; k < 32; k++) {
            float4 aq = *(const float4*)&As[k][r0];
            float4 bq = *(const float4*)&Bs[k][c0];
            float ar[4] = {aq.x, aq.y, aq.z, aq.w};
            float br[4] = {bq.x, bq.y, bq.z, bq.w};
            #pragma unroll
            for (int r = 0; r < 4; r++)
                #pragma unroll
                for (int c = 0; c < 4; c++)
                    acc[r][c] += ar[r] * br[c];
        }
        __syncthreads();
    }

    // write hs + reduce el/er
    const int bh = b * H + head;
    float* hsbase = g_hs + ((size_t)(bh * NN + bx * 64)) * COUT;
    float pl[4] = {}, pr[4] = {};
    #pragma unroll
    for (int r = 0; r < 4; r++) {
        float4 w = {acc[r][0], acc[r][1], acc[r][2], acc[r][3]};
        *(float4*)(hsbase + (size_t)(r0 + r) * COUT + c0) = w;
        #pragma unroll
        for (int c = 0; c < 4; c++) {
            float al = __ldg(a_l + c0 + c), ar_ = __ldg(a_r + c0 + c);
            pl[r] += acc[r][c] * al;
            pr[r] += acc[r][c] * ar_;
        }
    }
    #pragma unroll
    for (int r = 0; r < 4; r++) sred[cg][r0 + r] = pl[r];
    __syncthreads();
    if (tid < 64) {
        float s = 0.f;
        #pragma unroll
        for (int g = 0; g < 16; g++) s += sred[g][tid];
        g_el[(size_t)bh * NN + bx * 64 + tid] = s;
    }
    __syncthreads();
    #pragma unroll
    for (int r = 0; r < 4; r++) sred[cg][r0 + r] = pr[r];
    __syncthreads();
    if (tid < 64) {
        float s = 0.f;
        #pragma unroll
        for (int g = 0; g < 16; g++) s += sred[g][tid];
        g_er[(size_t)bh * NN + bx * 64 + tid] = s;
    }
}

// ---------------- K1b: E = max_j er ----------------
__global__ void k1b_max() {
    const int bh = blockIdx.x;
    __shared__ float sm[256];
    float m = -1e30f;
    for (int i = threadIdx.x; i < NN; i += 256)
        m = fmaxf(m, g_er[(size_t)bh * NN + i]);
    sm[threadIdx.x] = m;
    __syncthreads();
    for (int s = 128; s > 0; s >>= 1) {
        if (threadIdx.x < s) sm[threadIdx.x] = fmaxf(sm[threadIdx.x], sm[threadIdx.x + s]);
        __syncthreads();
    }
    if (threadIdx.x == 0) g_emax[bh] = sm[0];
}

// ---------------- K2: fused masked-softmax attention + P@V ----------------
__global__ __launch_bounds__(256, 2) void k2_attn(const float* __restrict__ adjs,
                                                  float* __restrict__ out) {
    const int it0  = blockIdx.x * TI;
    const int head = blockIdx.y;
    const int b    = blockIdx.z;
    const int bh   = b * H + head;
    const int tid  = threadIdx.x;

    extern __shared__ float smem[];
    float* sP   = smem;                 // [TJ][TIP] transposed P
    float* sHS  = sP + TJ * TIP;        // [TJ][COUT]
    float* sel  = sHS + TJ * COUT;      // [TI]
    float* selm = sel + TI;             // [TI] row shift m_i
    float* ser  = selm + TI;            // [TJ]
    float* sl   = ser + TJ;             // [TI] 1/l
    float* sred = sl + TI;              // [256]

    const int ig = tid >> 3, dg = tid & 7;
    const int i0 = ig * 4, d0 = dg * 8;

    // per-row shift m_i = leaky(el_i + E)  (upper bound over all j)
    {
        float E = g_emax[bh];
        if (tid < TI) {
            float e = g_el[(size_t)bh * NN + it0 + tid];
            sel[tid] = e;
            float s = e + E;
            selm[tid] = fmaxf(s, 0.1f * s);
        }
    }

    unsigned long long acc[4][4];
    #pragma unroll
    for (int r = 0; r < 4; r++)
        #pragma unroll
        for (int c = 0; c < 4; c++) acc[r][c] = 0ull;
    float lacc = 0.f;

    const float* abase = adjs + ((size_t)(b * NN + it0)) * NN;
    const int li = tid & 127;        // row for l-pass
    const int ljb = (tid >> 7) * 64; // j chunk for l-pass

    for (int jt = 0; jt < NN; jt += TJ) {
        __syncthreads();   // previous GEMM done before overwriting tiles
        // hs tile [TJ][COUT]
        {
            const float4* src = (const float4*)(g_hs + ((size_t)(bh * NN + jt)) * COUT);
            float4* dst = (float4*)sHS;
            #pragma unroll
            for (int t = 0; t < 8; t++) dst[tid + t * 256] = src[tid + t * 256];
        }
        if (tid < TJ) ser[tid] = g_er[(size_t)bh * NN + jt + tid];
        __syncthreads();

        // P build: p = adj * exp(leaky(el+er) - m_i), transposed store
        #pragma unroll 4
        for (int t = 0; t < 64; t++) {
            int idx = t * 256 + tid;
            int i = idx >> 7;
            int j = idx & 127;
            float a = __ldg(abase + (size_t)i * NN + jt + j);
            float s = sel[i] + ser[j];
            s = fmaxf(s, 0.1f * s);
            float p = a * __expf(s - selm[i]);
            sP[j * TIP + i] = p;
        }
        __syncthreads();

        // row-sum pass (read-only on sP, no sync needed vs GEMM)
        {
            float s = 0.f;
            #pragma unroll 8
            for (int j = 0; j < 64; j++) s += sP[(ljb + j) * TIP + li];
            lacc += s;
        }

        // O += P @ HS  (FFMA2 packed fp32)
        #pragma unroll 4
        for (int k = 0; k < TJ; k++) {
            const float* pcol = sP + k * TIP + i0;
            unsigned long long q0 = pack2(pcol[0]);
            unsigned long long q1 = pack2(pcol[1]);
            unsigned long long q2 = pack2(pcol[2]);
            unsigned long long q3 = pack2(pcol[3]);
            ulonglong2 h01 = *(const ulonglong2*)(sHS + k * COUT + d0);
            ulonglong2 h23 = *(const ulonglong2*)(sHS + k * COUT + d0 + 4);
            ffma2(acc[0][0], q0, h01.x); ffma2(acc[0][1], q0, h01.y);
            ffma2(acc[0][2], q0, h23.x); ffma2(acc[0][3], q0, h23.y);
            ffma2(acc[1][0], q1, h01.x); ffma2(acc[1][1], q1, h01.y);
            ffma2(acc[1][2], q1, h23.x); ffma2(acc[1][3], q1, h23.y);
            ffma2(acc[2][0], q2, h01.x); ffma2(acc[2][1], q2, h01.y);
            ffma2(acc[2][2], q2, h23.x); ffma2(acc[2][3], q2, h23.y);
            ffma2(acc[3][0], q3, h01.x); ffma2(acc[3][1], q3, h01.y);
            ffma2(acc[3][2], q3, h23.x); ffma2(acc[3][3], q3, h23.y);
        }
    }

    // combine l halves, invert
    __syncthreads();
    sred[tid] = lacc;
    __syncthreads();
    if (tid < 128) {
        float l = sred[tid] + sred[tid + 128];
        sl[tid] = (l > 0.f) ? (1.f / l) : 0.f;
    }
    __syncthreads();

    // epilogue: out[b][i][head*64+d] = acc / l
    float* obase = out + ((size_t)(b * NN + it0)) * HD + head * COUT;
    #pragma unroll
    for (int r = 0; r < 4; r++) {
        float inv = sl[i0 + r];
        float2 v0 = unpack2(acc[r][0]);
        float2 v1 = unpack2(acc[r][1]);
        float2 v2 = unpack2(acc[r][2]);
        float2 v3 = unpack2(acc[r][3]);
        float4 w0 = {v0.x * inv, v0.y * inv, v1.x * inv, v1.y * inv};
        float4 w1 = {v2.x * inv, v2.y * inv, v3.x * inv, v3.y * inv};
        float* op = obase + (size_t)(i0 + r) * HD + d0;
        *(float4*)op = w0;
        *(float4*)(op + 4) = w1;
    }
}

static const int SMEM_K2 = (TJ * TIP + TJ * COUT + TI * 4 + 256) * (int)sizeof(float);

extern "C" void kernel_launch(void* const* d_in, const int* in_sizes, int n_in,
                              void* d_out, int out_size) {
    const float* xs   = (const float*)d_in[0];
    const float* adjs = (const float*)d_in[1];
    const float* W1   = (const float*)d_in[2];
    const float* a_l  = (const float*)d_in[3];
    const float* a_r  = (const float*)d_in[4];
    float* out = (float*)d_out;

    cudaFuncSetAttribute(k2_attn, cudaFuncAttributeMaxDynamicSharedMemorySize, SMEM_K2);

    k1_gemm<<<dim3(32, 4, 4), 256>>>(xs, W1, a_l, a_r);
    k1b_max<<<16, 256>>>();
    k2_attn<<<dim3(16, 4, 4), 256, SMEM_K2>>>(adjs, out);
}